// round 10
// baseline (speedup 1.0000x reference)
#include <cuda_runtime.h>
#include <cuda_fp16.h>
#include <cstdint>

// ===========================================================================
// QuIP#-style quantized linear, GB300 (harness compiles at base sm_103 —
// tcgen05 unavailable, so the GEMM uses mma.sync fp16 HMMA, fp32 accum).
//   z = fwht( fwht(in/scaleWH*SU) @ (Wscale*W_hat + A@B)^T ) * SV
// K1 prep_w : dequant codebook + fold Wscale + fold A@B -> fp16 W_eff
// K2 prep_x : diag scale + FWHT-4096 per row           -> fp16 x
// K3 gemm   : 128x256 CTA tile, BK=64, 3-stage cp.async, mma.m16n8k16
// K4 epi    : FWHT-4096 per row + SV -> d_out (fp32)
// ===========================================================================

#define N_ROWS   8192
#define N_IN     4096
#define N_OUT    4096

#define CTA_M 128
#define CTA_N 256
#define BK    64
#define NSTEP (N_IN / BK)                 // 64
#define STAGE_ROWS (CTA_M + CTA_N)        // 384
#define STAGE_BYTES (STAGE_ROWS * 128)    // 49152 (each row: 64 halfs = 128B)
#define NSTAGE 3
#define SMEM_GEMM (NSTAGE * STAGE_BYTES)  // 147456

// ---------------- device scratch (static; no allocs allowed) ----------------
__device__ __half g_x[(size_t)N_ROWS * N_IN];
__device__ __half g_w[(size_t)N_OUT * N_IN];
__device__ float  g_z[(size_t)N_ROWS * N_OUT];

// ---------------- PTX helpers ----------------
__device__ __forceinline__ uint32_t smem_u32(const void* p) {
    uint32_t a;
    asm("{ .reg .u64 t; cvta.to.shared.u64 t, %1; cvt.u32.u64 %0, t; }"
        : "=r"(a) : "l"(p));
    return a;
}
__device__ __forceinline__ void cp_async16(uint32_t saddr, const void* gaddr) {
    asm volatile("cp.async.cg.shared.global [%0], [%1], 16;"
                 :: "r"(saddr), "l"(gaddr) : "memory");
}
__device__ __forceinline__ void ldsm4(uint32_t* r, uint32_t addr) {
    asm volatile("ldmatrix.sync.aligned.m8n8.x4.shared.b16 {%0,%1,%2,%3}, [%4];"
                 : "=r"(r[0]), "=r"(r[1]), "=r"(r[2]), "=r"(r[3]) : "r"(addr));
}
__device__ __forceinline__ void mma16816(float* c, const uint32_t* a, const uint32_t* b) {
    asm volatile(
        "mma.sync.aligned.m16n8k16.row.col.f32.f16.f16.f32 "
        "{%0,%1,%2,%3}, {%4,%5,%6,%7}, {%8,%9}, {%0,%1,%2,%3};"
        : "+f"(c[0]), "+f"(c[1]), "+f"(c[2]), "+f"(c[3])
        : "r"(a[0]), "r"(a[1]), "r"(a[2]), "r"(a[3]), "r"(b[0]), "r"(b[1]));
}

// ===========================================================================
// K1: W_eff = Wscale*D4_CB[Qidxs] + A@B  ->  g_w (fp16)
// CTA tile: 64 out x 64 in; 256 threads, each a 4x4 micro-tile.
// ===========================================================================
__global__ __launch_bounds__(256) void prep_w_kernel(
    const int*   __restrict__ Qidxs,   // [N_OUT][1024]
    const float* __restrict__ CB,      // [256][4]
    const float* __restrict__ Wsc,     // [1]
    const float* __restrict__ A,       // [N_OUT][64]
    const float* __restrict__ B)       // [64][N_IN]
{
    __shared__ float As[64 * 64];      // [o_local][r]
    __shared__ float Bs[64 * 64];      // [r][i_local]
    __shared__ float CBs[1024];

    const int i0 = blockIdx.x * 64;
    const int o0 = blockIdx.y * 64;
    const int tid = threadIdx.x;

    for (int idx = tid; idx < 64 * 64; idx += 256)
        As[idx] = A[(size_t)(o0 + (idx >> 6)) * 64 + (idx & 63)];
    for (int idx = tid; idx < 64 * 64; idx += 256)
        Bs[idx] = B[(size_t)(idx >> 6) * N_IN + i0 + (idx & 63)];
    for (int idx = tid; idx < 1024; idx += 256)
        CBs[idx] = CB[idx];
    __syncthreads();

    const float ws = Wsc[0];
    const int ob = (tid >> 4) * 4;
    const int ib = (tid & 15) * 4;

    float acc[4][4];
#pragma unroll
    for (int m = 0; m < 4; ++m)
#pragma unroll
        for (int j = 0; j < 4; ++j) acc[m][j] = 0.0f;

#pragma unroll 8
    for (int r = 0; r < 64; ++r) {
        float av[4], bv[4];
#pragma unroll
        for (int m = 0; m < 4; ++m) av[m] = As[(ob + m) * 64 + r];
#pragma unroll
        for (int j = 0; j < 4; ++j) bv[j] = Bs[r * 64 + ib + j];
#pragma unroll
        for (int m = 0; m < 4; ++m)
#pragma unroll
            for (int j = 0; j < 4; ++j) acc[m][j] = fmaf(av[m], bv[j], acc[m][j]);
    }

#pragma unroll
    for (int m = 0; m < 4; ++m) {
        const int o = o0 + ob + m;
        const int q = Qidxs[(size_t)o * (N_IN / 4) + ((i0 + ib) >> 2)];
#pragma unroll
        for (int j = 0; j < 4; ++j) {
            const int i = i0 + ib + j;
            float w = fmaf(ws, CBs[(q << 2) + j], acc[m][j]);
            g_w[(size_t)o * N_IN + i] = __float2half_rn(w);
        }
    }
}

// ===========================================================================
// K2: x = fwht(in*SU/scaleWH) -> g_x (fp16). One CTA per row.
// ===========================================================================
__global__ __launch_bounds__(512) void prep_x_kernel(
    const float* __restrict__ in,
    const float* __restrict__ SU,
    const float* __restrict__ scaleWH)
{
    __shared__ float s[4096];
    const int row = blockIdx.x, tid = threadIdx.x;
    const size_t base = (size_t)row * N_IN;

    for (int i = tid; i < 4096; i += 512)
        s[i] = in[base + i] * SU[i] / scaleWH[i];
    __syncthreads();

    for (int hb = 0; hb < 12; ++hb) {
        const int h = 1 << hb;
#pragma unroll
        for (int pp = 0; pp < 4; ++pp) {
            const int p = tid + pp * 512;
            const int ii = ((p >> hb) << (hb + 1)) | (p & (h - 1));
            float a = s[ii], b = s[ii + h];
            s[ii] = a + b;
            s[ii + h] = a - b;
        }
        __syncthreads();
    }

    const float inv = 0.015625f;   // 1/sqrt(4096)
    for (int i = tid; i < 4096; i += 512)
        g_x[base + i] = __float2half_rn(s[i] * inv);
}

// ===========================================================================
// K3: GEMM  g_z = g_x (8192x4096) * g_w^T (4096x4096), fp16 in / fp32 acc.
// Smem stage: rows 0..127 = A (X tile), rows 128..383 = B (W tile).
// Row = 64 halfs = 128B; 16B chunk c at row r stored at (c ^ (r&7)) -> both
// cp.async stores and ldmatrix reads are bank-conflict-free.
// ===========================================================================
__device__ __forceinline__ void issue_stage(int tid, int m0, int n0,
                                            int step, int buf, uint32_t sb) {
    const int kb = step * BK;
    const uint32_t base = sb + buf * STAGE_BYTES;
#pragma unroll
    for (int i = 0; i < (STAGE_ROWS * 8) / 256; ++i) {   // 12
        const int idx = tid + i * 256;
        const int row = idx >> 3;
        const int ch  = idx & 7;
        const uint32_t saddr = base + row * 128 + ((ch ^ (row & 7)) << 4);
        const __half* g = (row < CTA_M)
            ? g_x + (size_t)(m0 + row) * N_IN + kb + ch * 8
            : g_w + (size_t)(n0 + row - CTA_M) * N_IN + kb + ch * 8;
        cp_async16(saddr, g);
    }
    asm volatile("cp.async.commit_group;" ::: "memory");
}

__global__ __launch_bounds__(256) void gemm_kernel() {
    extern __shared__ char smem[];
    const uint32_t sb = smem_u32(smem);
    const int tid  = threadIdx.x;
    const int lane = tid & 31;
    const int wid  = tid >> 5;
    const int wm   = wid >> 2;          // 0..1
    const int wn   = wid & 3;           // 0..3
    const int m0   = blockIdx.y * CTA_M;
    const int n0   = blockIdx.x * CTA_N;

    const int rl = lane & 15;           // ldmatrix row within 16-row tile
    const int cl = lane >> 4;           // ldmatrix 16B-chunk select (0/1)
    const int sx = rl & 7;              // swizzle factor (same for A and B)

    float acc[4][8][4];
#pragma unroll
    for (int mi = 0; mi < 4; ++mi)
#pragma unroll
        for (int ni = 0; ni < 8; ++ni)
#pragma unroll
            for (int q = 0; q < 4; ++q) acc[mi][ni][q] = 0.0f;

    issue_stage(tid, m0, n0, 0, 0, sb);
    issue_stage(tid, m0, n0, 1, 1, sb);

    const uint32_t Abase0 = sb + (uint32_t)(wm * 64 + rl) * 128;
    const uint32_t Bbase0 = sb + (uint32_t)(CTA_M + wn * 64 + rl) * 128;

    for (int step = 0; step < NSTEP; ++step) {
        const int buf = step % NSTAGE;
        if (step < NSTEP - 1) {
            asm volatile("cp.async.wait_group 1;" ::: "memory");
        } else {
            asm volatile("cp.async.wait_group 0;" ::: "memory");
        }
        __syncthreads();
        if (step + 2 < NSTEP)
            issue_stage(tid, m0, n0, step + 2, (step + 2) % NSTAGE, sb);

        const uint32_t Ab = Abase0 + buf * STAGE_BYTES;
        const uint32_t Bb = Bbase0 + buf * STAGE_BYTES;

#pragma unroll
        for (int kk = 0; kk < 4; ++kk) {
            const uint32_t co = (uint32_t)(((kk * 2 + cl) ^ sx) << 4);
            uint32_t a[4][4];
#pragma unroll
            for (int mi = 0; mi < 4; ++mi)
                ldsm4(a[mi], Ab + mi * 16 * 128 + co);
            uint32_t b[8][2];
#pragma unroll
            for (int nj = 0; nj < 4; ++nj) {
                uint32_t r[4];
                ldsm4(r, Bb + nj * 16 * 128 + co);
                b[2 * nj][0]     = r[0];
                b[2 * nj + 1][0] = r[1];
                b[2 * nj][1]     = r[2];
                b[2 * nj + 1][1] = r[3];
            }
#pragma unroll
            for (int mi = 0; mi < 4; ++mi)
#pragma unroll
                for (int ni = 0; ni < 8; ++ni)
                    mma16816(acc[mi][ni], a[mi], b[ni]);
        }
    }

    // epilogue: write fp32 tile to g_z
    const int rbase = m0 + wm * 64 + (lane >> 2);
    const int cbase = n0 + wn * 64 + (lane & 3) * 2;
#pragma unroll
    for (int mi = 0; mi < 4; ++mi) {
#pragma unroll
        for (int ni = 0; ni < 8; ++ni) {
            float* p0 = &g_z[(size_t)(rbase + mi * 16) * N_OUT + cbase + ni * 8];
            float* p1 = &g_z[(size_t)(rbase + mi * 16 + 8) * N_OUT + cbase + ni * 8];
            p0[0] = acc[mi][ni][0];  p0[1] = acc[mi][ni][1];
            p1[0] = acc[mi][ni][2];  p1[1] = acc[mi][ni][3];
        }
    }
}

// ===========================================================================
// K4: out = fwht(z) * SV. One CTA per row.
// ===========================================================================
__global__ __launch_bounds__(512) void epi_kernel(
    const float* __restrict__ SV, float* __restrict__ out)
{
    __shared__ float s[4096];
    const int row = blockIdx.x, tid = threadIdx.x;
    const size_t base = (size_t)row * N_OUT;

    for (int i = tid; i < 4096; i += 512) s[i] = g_z[base + i];
    __syncthreads();

    for (int hb = 0; hb < 12; ++hb) {
        const int h = 1 << hb;
#pragma unroll
        for (int pp = 0; pp < 4; ++pp) {
            const int p = tid + pp * 512;
            const int ii = ((p >> hb) << (hb + 1)) | (p & (h - 1));
            float a = s[ii], b = s[ii + h];
            s[ii] = a + b;
            s[ii + h] = a - b;
        }
        __syncthreads();
    }

    const float inv = 0.015625f;
    for (int i = tid; i < 4096; i += 512)
        out[base + i] = s[i] * inv * SV[i];
}

// ===========================================================================
// launch (no static state: unconditional, deterministic every call)
// ===========================================================================
extern "C" void kernel_launch(void* const* d_in, const int* in_sizes, int n_args,
                              void* d_out, int out_size) {
    (void)in_sizes; (void)n_args; (void)out_size;
    const float* input   = (const float*)d_in[0];
    const int*   Qidxs   = (const int*)  d_in[1];
    const float* D4_CB   = (const float*)d_in[2];
    const float* SU      = (const float*)d_in[3];
    const float* SV      = (const float*)d_in[4];
    const float* Wscale  = (const float*)d_in[5];
    const float* A       = (const float*)d_in[6];
    const float* B       = (const float*)d_in[7];
    const float* scaleWH = (const float*)d_in[8];
    float* out = (float*)d_out;

    cudaFuncSetAttribute(gemm_kernel,
                         cudaFuncAttributeMaxDynamicSharedMemorySize, SMEM_GEMM);

    prep_w_kernel<<<dim3(N_IN / 64, N_OUT / 64), 256>>>(Qidxs, D4_CB, Wscale, A, B);
    prep_x_kernel<<<N_ROWS, 512>>>(input, SU, scaleWH);
    gemm_kernel<<<dim3(N_OUT / CTA_N, N_ROWS / CTA_M), 256, SMEM_GEMM>>>();
    epi_kernel<<<N_ROWS, 512>>>(SV, out);
}

// round 11
// speedup vs baseline: 1.1490x; 1.1490x over previous
#include <cuda_runtime.h>
#include <cuda_fp16.h>
#include <cstdint>

// ===========================================================================
// QuIP#-style quantized linear, GB300 (base sm_103 target -> mma.sync HMMA).
//   z = fwht( fwht(in/scaleWH*SU) @ (Wscale*W_hat + A@B)^T ) * SV
// K1 prep_w : dequant codebook + fold Wscale + fold A@B -> fp16 W_eff
// K2 prep_x : diag scale + reg/shuffle FWHT-4096 -> fp16 x
// K3 gemm   : 128x256 CTA tile, BK=64, 3-stage cp.async, mma.m16n8k16
// K4 epi    : reg/shuffle FWHT-4096 + SV -> d_out (fp32)
// FWHT scheme (per 4096-row, 256 threads x 16 regs):
//   lv 0-3  dist 1..8    : local (16 consecutive elems per thread)
//   lv 4-7  dist 16..128 : __shfl_xor m=1,2,4,8
//   padded smem transpose (conflict-free both ways)
//   lv 8-11 dist 256..2048: local on strided layout (j^1,2,4,8)
// ===========================================================================

#define N_ROWS   8192
#define N_IN     4096
#define N_OUT    4096

#define CTA_M 128
#define CTA_N 256
#define BK    64
#define NSTEP (N_IN / BK)                 // 64
#define STAGE_ROWS (CTA_M + CTA_N)        // 384
#define STAGE_BYTES (STAGE_ROWS * 128)    // 49152
#define NSTAGE 3
#define SMEM_GEMM (NSTAGE * STAGE_BYTES)  // 147456

// ---------------- device scratch ----------------
__device__ __half g_x[(size_t)N_ROWS * N_IN];
__device__ __half g_w[(size_t)N_OUT * N_IN];
__device__ float  g_z[(size_t)N_ROWS * N_OUT];

// ---------------- PTX helpers ----------------
__device__ __forceinline__ uint32_t smem_u32(const void* p) {
    uint32_t a;
    asm("{ .reg .u64 t; cvta.to.shared.u64 t, %1; cvt.u32.u64 %0, t; }"
        : "=r"(a) : "l"(p));
    return a;
}
__device__ __forceinline__ void cp_async16(uint32_t saddr, const void* gaddr) {
    asm volatile("cp.async.cg.shared.global [%0], [%1], 16;"
                 :: "r"(saddr), "l"(gaddr) : "memory");
}
__device__ __forceinline__ void ldsm4(uint32_t* r, uint32_t addr) {
    asm volatile("ldmatrix.sync.aligned.m8n8.x4.shared.b16 {%0,%1,%2,%3}, [%4];"
                 : "=r"(r[0]), "=r"(r[1]), "=r"(r[2]), "=r"(r[3]) : "r"(addr));
}
__device__ __forceinline__ void mma16816(float* c, const uint32_t* a, const uint32_t* b) {
    asm volatile(
        "mma.sync.aligned.m16n8k16.row.col.f32.f16.f16.f32 "
        "{%0,%1,%2,%3}, {%4,%5,%6,%7}, {%8,%9}, {%0,%1,%2,%3};"
        : "+f"(c[0]), "+f"(c[1]), "+f"(c[2]), "+f"(c[3])
        : "r"(a[0]), "r"(a[1]), "r"(a[2]), "r"(a[3]), "r"(b[0]), "r"(b[1]));
}

// ---------------- register/shuffle FWHT core (4096 pts, 256 threads) -------
// v[16] per thread. Phase A layout: elem = 16*t + j.  After transpose:
// elem = t + 256*j.  Padded smem index: idx + (idx >> 5).
__device__ __forceinline__ void fwht_local16(float* v, int dist_lo, int dist_hi) {
#pragma unroll
    for (int d = dist_lo; d <= dist_hi; d <<= 1) {
#pragma unroll
        for (int j = 0; j < 16; ++j) {
            if (!(j & d)) {
                float a = v[j], b = v[j | d];
                v[j]     = a + b;
                v[j | d] = a - b;
            }
        }
    }
}
__device__ __forceinline__ void fwht_shfl(float* v, int t) {
#pragma unroll
    for (int m = 1; m <= 8; m <<= 1) {
        const bool hi = (t & m) != 0;
#pragma unroll
        for (int j = 0; j < 16; ++j) {
            float o = __shfl_xor_sync(0xffffffffu, v[j], m);
            v[j] = hi ? (o - v[j]) : (v[j] + o);
        }
    }
}
__device__ __forceinline__ void fwht_transpose(float* v, float* s, int t) {
#pragma unroll
    for (int j = 0; j < 16; ++j) {
        int idx = 16 * t + j;
        s[idx + (idx >> 5)] = v[j];
    }
    __syncthreads();
#pragma unroll
    for (int j = 0; j < 16; ++j) {
        int idx = t + 256 * j;
        v[j] = s[idx + (idx >> 5)];
    }
}

// ===========================================================================
// K1: W_eff = Wscale*D4_CB[Qidxs] + A@B  ->  g_w (fp16)
// ===========================================================================
__global__ __launch_bounds__(256) void prep_w_kernel(
    const int*   __restrict__ Qidxs,   // [N_OUT][1024]
    const float* __restrict__ CB,      // [256][4]
    const float* __restrict__ Wsc,     // [1]
    const float* __restrict__ A,       // [N_OUT][64]
    const float* __restrict__ B)       // [64][N_IN]
{
    __shared__ float As[64 * 64];
    __shared__ float Bs[64 * 64];
    __shared__ float CBs[1024];

    const int i0 = blockIdx.x * 64;
    const int o0 = blockIdx.y * 64;
    const int tid = threadIdx.x;

    for (int idx = tid; idx < 64 * 64; idx += 256)
        As[idx] = A[(size_t)(o0 + (idx >> 6)) * 64 + (idx & 63)];
    for (int idx = tid; idx < 64 * 64; idx += 256)
        Bs[idx] = B[(size_t)(idx >> 6) * N_IN + i0 + (idx & 63)];
    for (int idx = tid; idx < 1024; idx += 256)
        CBs[idx] = CB[idx];
    __syncthreads();

    const float ws = Wsc[0];
    const int ob = (tid >> 4) * 4;
    const int ib = (tid & 15) * 4;

    float acc[4][4];
#pragma unroll
    for (int m = 0; m < 4; ++m)
#pragma unroll
        for (int j = 0; j < 4; ++j) acc[m][j] = 0.0f;

#pragma unroll 8
    for (int r = 0; r < 64; ++r) {
        float av[4], bv[4];
#pragma unroll
        for (int m = 0; m < 4; ++m) av[m] = As[(ob + m) * 64 + r];
#pragma unroll
        for (int j = 0; j < 4; ++j) bv[j] = Bs[r * 64 + ib + j];
#pragma unroll
        for (int m = 0; m < 4; ++m)
#pragma unroll
            for (int j = 0; j < 4; ++j) acc[m][j] = fmaf(av[m], bv[j], acc[m][j]);
    }

#pragma unroll
    for (int m = 0; m < 4; ++m) {
        const int o = o0 + ob + m;
        const int q = Qidxs[(size_t)o * (N_IN / 4) + ((i0 + ib) >> 2)];
#pragma unroll
        for (int j = 0; j < 4; ++j) {
            const int i = i0 + ib + j;
            float w = fmaf(ws, CBs[(q << 2) + j], acc[m][j]);
            g_w[(size_t)o * N_IN + i] = __float2half_rn(w);
        }
    }
}

// ===========================================================================
// K2: x = fwht(in*SU/scaleWH) -> g_x (fp16). One CTA (256 thr) per row.
// ===========================================================================
__global__ __launch_bounds__(256) void prep_x_kernel(
    const float* __restrict__ in,
    const float* __restrict__ SU,
    const float* __restrict__ scaleWH)
{
    __shared__ float s[4096 + 128];
    const int row = blockIdx.x, t = threadIdx.x;
    const size_t base = (size_t)row * N_IN;

    float v[16];
    const float4* ip = (const float4*)(in + base) + 4 * t;
    const float4* sp = (const float4*)SU + 4 * t;
    const float4* wp = (const float4*)scaleWH + 4 * t;
#pragma unroll
    for (int q = 0; q < 4; ++q) {
        float4 a = ip[q], su = sp[q], sw = wp[q];
        v[4 * q + 0] = a.x * su.x / sw.x;
        v[4 * q + 1] = a.y * su.y / sw.y;
        v[4 * q + 2] = a.z * su.z / sw.z;
        v[4 * q + 3] = a.w * su.w / sw.w;
    }

    fwht_local16(v, 1, 8);        // lv 0-3
    fwht_shfl(v, t);              // lv 4-7
    fwht_transpose(v, s, t);      // -> elem = t + 256*j
    fwht_local16(v, 1, 8);        // lv 8-11 (dist 256..2048)

    const float inv = 0.015625f;  // 1/sqrt(4096)
#pragma unroll
    for (int j = 0; j < 16; ++j)
        g_x[base + t + 256 * j] = __float2half_rn(v[j] * inv);
}

// ===========================================================================
// K3: GEMM  g_z = g_x (8192x4096) * g_w^T (4096x4096), fp16 in / fp32 acc.
// ===========================================================================
__device__ __forceinline__ void issue_stage(int tid, int m0, int n0,
                                            int step, int buf, uint32_t sb) {
    const int kb = step * BK;
    const uint32_t base = sb + buf * STAGE_BYTES;
#pragma unroll
    for (int i = 0; i < (STAGE_ROWS * 8) / 256; ++i) {   // 12
        const int idx = tid + i * 256;
        const int row = idx >> 3;
        const int ch  = idx & 7;
        const uint32_t saddr = base + row * 128 + ((ch ^ (row & 7)) << 4);
        const __half* g = (row < CTA_M)
            ? g_x + (size_t)(m0 + row) * N_IN + kb + ch * 8
            : g_w + (size_t)(n0 + row - CTA_M) * N_IN + kb + ch * 8;
        cp_async16(saddr, g);
    }
    asm volatile("cp.async.commit_group;" ::: "memory");
}

__global__ __launch_bounds__(256) void gemm_kernel() {
    extern __shared__ char smem[];
    const uint32_t sb = smem_u32(smem);
    const int tid  = threadIdx.x;
    const int lane = tid & 31;
    const int wid  = tid >> 5;
    const int wm   = wid >> 2;
    const int wn   = wid & 3;
    const int m0   = blockIdx.y * CTA_M;
    const int n0   = blockIdx.x * CTA_N;

    const int rl = lane & 15;
    const int cl = lane >> 4;
    const int sx = rl & 7;

    float acc[4][8][4];
#pragma unroll
    for (int mi = 0; mi < 4; ++mi)
#pragma unroll
        for (int ni = 0; ni < 8; ++ni)
#pragma unroll
            for (int q = 0; q < 4; ++q) acc[mi][ni][q] = 0.0f;

    issue_stage(tid, m0, n0, 0, 0, sb);
    issue_stage(tid, m0, n0, 1, 1, sb);

    const uint32_t Abase0 = sb + (uint32_t)(wm * 64 + rl) * 128;
    const uint32_t Bbase0 = sb + (uint32_t)(CTA_M + wn * 64 + rl) * 128;

    for (int step = 0; step < NSTEP; ++step) {
        const int buf = step % NSTAGE;
        if (step < NSTEP - 1) {
            asm volatile("cp.async.wait_group 1;" ::: "memory");
        } else {
            asm volatile("cp.async.wait_group 0;" ::: "memory");
        }
        __syncthreads();
        if (step + 2 < NSTEP)
            issue_stage(tid, m0, n0, step + 2, (step + 2) % NSTAGE, sb);

        const uint32_t Ab = Abase0 + buf * STAGE_BYTES;
        const uint32_t Bb = Bbase0 + buf * STAGE_BYTES;

#pragma unroll
        for (int kk = 0; kk < 4; ++kk) {
            const uint32_t co = (uint32_t)(((kk * 2 + cl) ^ sx) << 4);
            uint32_t a[4][4];
#pragma unroll
            for (int mi = 0; mi < 4; ++mi)
                ldsm4(a[mi], Ab + mi * 16 * 128 + co);
            uint32_t b[8][2];
#pragma unroll
            for (int nj = 0; nj < 4; ++nj) {
                uint32_t r[4];
                ldsm4(r, Bb + nj * 16 * 128 + co);
                b[2 * nj][0]     = r[0];
                b[2 * nj + 1][0] = r[1];
                b[2 * nj][1]     = r[2];
                b[2 * nj + 1][1] = r[3];
            }
#pragma unroll
            for (int mi = 0; mi < 4; ++mi)
#pragma unroll
                for (int ni = 0; ni < 8; ++ni)
                    mma16816(acc[mi][ni], a[mi], b[ni]);
        }
    }

    const int rbase = m0 + wm * 64 + (lane >> 2);
    const int cbase = n0 + wn * 64 + (lane & 3) * 2;
#pragma unroll
    for (int mi = 0; mi < 4; ++mi) {
#pragma unroll
        for (int ni = 0; ni < 8; ++ni) {
            float* p0 = &g_z[(size_t)(rbase + mi * 16) * N_OUT + cbase + ni * 8];
            float* p1 = &g_z[(size_t)(rbase + mi * 16 + 8) * N_OUT + cbase + ni * 8];
            p0[0] = acc[mi][ni][0];  p0[1] = acc[mi][ni][1];
            p1[0] = acc[mi][ni][2];  p1[1] = acc[mi][ni][3];
        }
    }
}

// ===========================================================================
// K4: out = fwht(z) * SV. One CTA (256 thr) per row.
// ===========================================================================
__global__ __launch_bounds__(256) void epi_kernel(
    const float* __restrict__ SV, float* __restrict__ out)
{
    __shared__ float s[4096 + 128];
    const int row = blockIdx.x, t = threadIdx.x;
    const size_t base = (size_t)row * N_OUT;

    float v[16];
    const float4* zp = (const float4*)(g_z + base) + 4 * t;
#pragma unroll
    for (int q = 0; q < 4; ++q) {
        float4 a = zp[q];
        v[4 * q + 0] = a.x;  v[4 * q + 1] = a.y;
        v[4 * q + 2] = a.z;  v[4 * q + 3] = a.w;
    }

    fwht_local16(v, 1, 8);        // lv 0-3
    fwht_shfl(v, t);              // lv 4-7
    fwht_transpose(v, s, t);      // -> elem = t + 256*j
    fwht_local16(v, 1, 8);        // lv 8-11

    const float inv = 0.015625f;
#pragma unroll
    for (int j = 0; j < 16; ++j) {
        const int e = t + 256 * j;
        out[base + e] = v[j] * inv * SV[e];
    }
}

// ===========================================================================
// launch
// ===========================================================================
extern "C" void kernel_launch(void* const* d_in, const int* in_sizes, int n_args,
                              void* d_out, int out_size) {
    (void)in_sizes; (void)n_args; (void)out_size;
    const float* input   = (const float*)d_in[0];
    const int*   Qidxs   = (const int*)  d_in[1];
    const float* D4_CB   = (const float*)d_in[2];
    const float* SU      = (const float*)d_in[3];
    const float* SV      = (const float*)d_in[4];
    const float* Wscale  = (const float*)d_in[5];
    const float* A       = (const float*)d_in[6];
    const float* B       = (const float*)d_in[7];
    const float* scaleWH = (const float*)d_in[8];
    float* out = (float*)d_out;

    cudaFuncSetAttribute(gemm_kernel,
                         cudaFuncAttributeMaxDynamicSharedMemorySize, SMEM_GEMM);

    prep_w_kernel<<<dim3(N_IN / 64, N_OUT / 64), 256>>>(Qidxs, D4_CB, Wscale, A, B);
    prep_x_kernel<<<N_ROWS, 256>>>(input, SU, scaleWH);
    gemm_kernel<<<dim3(N_OUT / CTA_N, N_ROWS / CTA_M), 256, SMEM_GEMM>>>();
    epi_kernel<<<N_ROWS, 256>>>(SV, out);
}

// round 13
// speedup vs baseline: 1.1698x; 1.0181x over previous
#include <cuda_runtime.h>
#include <cuda_fp16.h>
#include <cstdint>

// ===========================================================================
// QuIP#-style quantized linear, GB300 (base sm_103 target -> mma.sync HMMA).
//   z = fwht( fwht(in/scaleWH*SU) @ (Wscale*W_hat + A@B)^T ) * SV
// K1 prep   : [blocks 0..4095]  dequant + fold Wscale + fold A@B -> fp16 W_eff
//             [blocks 4096..]   diag scale + reg/shuffle FWHT (2 rows/CTA) -> fp16 x
// K2 gemm   : 128x256 CTA tile, BK=64, 3-stage cp.async, mma.m16n8k16
//             (measured at the mma.sync fp16 hardware floor: 512 MAC/cyc/SM)
// K3 epi    : reg/shuffle FWHT (2 rows/CTA) + SV -> d_out (fp32)
// ===========================================================================

#define N_ROWS   8192
#define N_IN     4096
#define N_OUT    4096

#define CTA_M 128
#define CTA_N 256
#define BK    64
#define NSTEP (N_IN / BK)                 // 64
#define STAGE_ROWS (CTA_M + CTA_N)        // 384
#define STAGE_BYTES (STAGE_ROWS * 128)    // 49152
#define NSTAGE 3
#define SMEM_GEMM (NSTAGE * STAGE_BYTES)  // 147456

// ---------------- device scratch ----------------
__device__ __half g_x[(size_t)N_ROWS * N_IN];
__device__ __half g_w[(size_t)N_OUT * N_IN];
__device__ float  g_z[(size_t)N_ROWS * N_OUT];

// ---------------- PTX helpers ----------------
__device__ __forceinline__ uint32_t smem_u32(const void* p) {
    uint32_t a;
    asm("{ .reg .u64 t; cvta.to.shared.u64 t, %1; cvt.u32.u64 %0, t; }"
        : "=r"(a) : "l"(p));
    return a;
}
__device__ __forceinline__ void cp_async16(uint32_t saddr, const void* gaddr) {
    asm volatile("cp.async.cg.shared.global [%0], [%1], 16;"
                 :: "r"(saddr), "l"(gaddr) : "memory");
}
__device__ __forceinline__ void ldsm4(uint32_t* r, uint32_t addr) {
    asm volatile("ldmatrix.sync.aligned.m8n8.x4.shared.b16 {%0,%1,%2,%3}, [%4];"
                 : "=r"(r[0]), "=r"(r[1]), "=r"(r[2]), "=r"(r[3]) : "r"(addr));
}
__device__ __forceinline__ void mma16816(float* c, const uint32_t* a, const uint32_t* b) {
    asm volatile(
        "mma.sync.aligned.m16n8k16.row.col.f32.f16.f16.f32 "
        "{%0,%1,%2,%3}, {%4,%5,%6,%7}, {%8,%9}, {%0,%1,%2,%3};"
        : "+f"(c[0]), "+f"(c[1]), "+f"(c[2]), "+f"(c[3])
        : "r"(a[0]), "r"(a[1]), "r"(a[2]), "r"(a[3]), "r"(b[0]), "r"(b[1]));
}

// ---------------- register/shuffle FWHT core (4096 pts, 256 threads) -------
__device__ __forceinline__ void fwht_local16(float* v) {
#pragma unroll
    for (int d = 1; d <= 8; d <<= 1) {
#pragma unroll
        for (int j = 0; j < 16; ++j) {
            if (!(j & d)) {
                float a = v[j], b = v[j | d];
                v[j]     = a + b;
                v[j | d] = a - b;
            }
        }
    }
}
__device__ __forceinline__ void fwht_shfl(float* v, int t) {
#pragma unroll
    for (int m = 1; m <= 8; m <<= 1) {
        const bool hi = (t & m) != 0;
#pragma unroll
        for (int j = 0; j < 16; ++j) {
            float o = __shfl_xor_sync(0xffffffffu, v[j], m);
            v[j] = hi ? (o - v[j]) : (v[j] + o);
        }
    }
}
// Two-row transpose through padded smem (one barrier covers both rows).
__device__ __forceinline__ void fwht_transpose2(float* v0, float* v1,
                                                float* s0, float* s1, int t) {
#pragma unroll
    for (int j = 0; j < 16; ++j) {
        int idx = 16 * t + j;
        s0[idx + (idx >> 5)] = v0[j];
        s1[idx + (idx >> 5)] = v1[j];
    }
    __syncthreads();
#pragma unroll
    for (int j = 0; j < 16; ++j) {
        int idx = t + 256 * j;
        v0[j] = s0[idx + (idx >> 5)];
        v1[j] = s1[idx + (idx >> 5)];
    }
}

// ===========================================================================
// K1: merged prep.  Blocks [0, 4096): W_eff tile (64 out x 64 in).
//                   Blocks [4096, 8192): x FWHT, 2 rows per CTA.
// ===========================================================================
#define PREP_W_BLOCKS 4096
#define PREP_SMEM_FLOATS 9216   // max(prep_w 9216, prep_x 2*4224=8448)

__device__ void prep_w_body(float* sm, int blk,
                            const int*   __restrict__ Qidxs,
                            const float* __restrict__ CB,
                            const float* __restrict__ Wsc,
                            const float* __restrict__ A,
                            const float* __restrict__ B)
{
    float* As  = sm;            // [64][64]
    float* Bs  = sm + 4096;     // [64][64]
    float* CBs = sm + 8192;     // [1024]

    const int i0 = (blk & 63) * 64;
    const int o0 = (blk >> 6) * 64;
    const int tid = threadIdx.x;

    for (int idx = tid; idx < 64 * 64; idx += 256)
        As[idx] = A[(size_t)(o0 + (idx >> 6)) * 64 + (idx & 63)];
    for (int idx = tid; idx < 64 * 64; idx += 256)
        Bs[idx] = B[(size_t)(idx >> 6) * N_IN + i0 + (idx & 63)];
    for (int idx = tid; idx < 1024; idx += 256)
        CBs[idx] = CB[idx];
    __syncthreads();

    const float ws = Wsc[0];
    const int ob = (tid >> 4) * 4;
    const int ib = (tid & 15) * 4;

    float acc[4][4];
#pragma unroll
    for (int m = 0; m < 4; ++m)
#pragma unroll
        for (int j = 0; j < 4; ++j) acc[m][j] = 0.0f;

#pragma unroll 8
    for (int r = 0; r < 64; ++r) {
        float av[4], bv[4];
#pragma unroll
        for (int m = 0; m < 4; ++m) av[m] = As[(ob + m) * 64 + r];
#pragma unroll
        for (int j = 0; j < 4; ++j) bv[j] = Bs[r * 64 + ib + j];
#pragma unroll
        for (int m = 0; m < 4; ++m)
#pragma unroll
            for (int j = 0; j < 4; ++j) acc[m][j] = fmaf(av[m], bv[j], acc[m][j]);
    }

#pragma unroll
    for (int m = 0; m < 4; ++m) {
        const int o = o0 + ob + m;
        const int q = Qidxs[(size_t)o * (N_IN / 4) + ((i0 + ib) >> 2)];
#pragma unroll
        for (int j = 0; j < 4; ++j) {
            const int i = i0 + ib + j;
            float w = fmaf(ws, CBs[(q << 2) + j], acc[m][j]);
            g_w[(size_t)o * N_IN + i] = __float2half_rn(w);
        }
    }
}

__device__ void prep_x_body(float* sm, int blk,
                            const float* __restrict__ in,
                            const float* __restrict__ SU,
                            const float* __restrict__ scaleWH)
{
    float* s0 = sm;
    float* s1 = sm + 4224;
    const int t = threadIdx.x;
    const size_t b0 = (size_t)(2 * blk)     * N_IN;
    const size_t b1 = (size_t)(2 * blk + 1) * N_IN;

    float v0[16], v1[16], su[16], sw[16];
    const float4* sp = (const float4*)SU + 4 * t;
    const float4* wp = (const float4*)scaleWH + 4 * t;
    const float4* i0p = (const float4*)(in + b0) + 4 * t;
    const float4* i1p = (const float4*)(in + b1) + 4 * t;
#pragma unroll
    for (int q = 0; q < 4; ++q) {
        float4 a = sp[q]; su[4*q]=a.x; su[4*q+1]=a.y; su[4*q+2]=a.z; su[4*q+3]=a.w;
        float4 c = wp[q]; sw[4*q]=c.x; sw[4*q+1]=c.y; sw[4*q+2]=c.z; sw[4*q+3]=c.w;
    }
#pragma unroll
    for (int q = 0; q < 4; ++q) {
        float4 a = i0p[q], c = i1p[q];
        v0[4*q]=a.x; v0[4*q+1]=a.y; v0[4*q+2]=a.z; v0[4*q+3]=a.w;
        v1[4*q]=c.x; v1[4*q+1]=c.y; v1[4*q+2]=c.z; v1[4*q+3]=c.w;
    }
#pragma unroll
    for (int j = 0; j < 16; ++j) {
        float f = su[j] / sw[j];
        v0[j] *= f;
        v1[j] *= f;
    }

    fwht_local16(v0); fwht_local16(v1);
    fwht_shfl(v0, t); fwht_shfl(v1, t);
    fwht_transpose2(v0, v1, s0, s1, t);
    fwht_local16(v0); fwht_local16(v1);

    const float inv = 0.015625f;  // 1/sqrt(4096)
#pragma unroll
    for (int j = 0; j < 16; ++j) {
        g_x[b0 + t + 256 * j] = __float2half_rn(v0[j] * inv);
        g_x[b1 + t + 256 * j] = __float2half_rn(v1[j] * inv);
    }
}

__global__ __launch_bounds__(256) void prep_kernel(
    const int*   __restrict__ Qidxs,
    const float* __restrict__ CB,
    const float* __restrict__ Wsc,
    const float* __restrict__ A,
    const float* __restrict__ B,
    const float* __restrict__ in,
    const float* __restrict__ SU,
    const float* __restrict__ scaleWH)
{
    __shared__ float sm[PREP_SMEM_FLOATS];
    const int blk = blockIdx.x;
    if (blk < PREP_W_BLOCKS)
        prep_w_body(sm, blk, Qidxs, CB, Wsc, A, B);
    else
        prep_x_body(sm, blk - PREP_W_BLOCKS, in, SU, scaleWH);
}

// ===========================================================================
// K2: GEMM  g_z = g_x (8192x4096) * g_w^T (4096x4096), fp16 in / fp32 acc.
// ===========================================================================
__device__ __forceinline__ void issue_stage(int tid, int m0, int n0,
                                            int step, int buf, uint32_t sb) {
    const int kb = step * BK;
    const uint32_t base = sb + buf * STAGE_BYTES;
#pragma unroll
    for (int i = 0; i < (STAGE_ROWS * 8) / 256; ++i) {   // 12
        const int idx = tid + i * 256;
        const int row = idx >> 3;
        const int ch  = idx & 7;
        const uint32_t saddr = base + row * 128 + ((ch ^ (row & 7)) << 4);
        const __half* g = (row < CTA_M)
            ? g_x + (size_t)(m0 + row) * N_IN + kb + ch * 8
            : g_w + (size_t)(n0 + row - CTA_M) * N_IN + kb + ch * 8;
        cp_async16(saddr, g);
    }
    asm volatile("cp.async.commit_group;" ::: "memory");
}

__global__ __launch_bounds__(256) void gemm_kernel() {
    extern __shared__ char smem[];
    const uint32_t sb = smem_u32(smem);
    const int tid  = threadIdx.x;
    const int lane = tid & 31;
    const int wid  = tid >> 5;
    const int wm   = wid >> 2;
    const int wn   = wid & 3;
    const int m0   = blockIdx.y * CTA_M;
    const int n0   = blockIdx.x * CTA_N;

    const int rl = lane & 15;
    const int cl = lane >> 4;
    const int sx = rl & 7;

    float acc[4][8][4];
#pragma unroll
    for (int mi = 0; mi < 4; ++mi)
#pragma unroll
        for (int ni = 0; ni < 8; ++ni)
#pragma unroll
            for (int q = 0; q < 4; ++q) acc[mi][ni][q] = 0.0f;

    issue_stage(tid, m0, n0, 0, 0, sb);
    issue_stage(tid, m0, n0, 1, 1, sb);

    const uint32_t Abase0 = sb + (uint32_t)(wm * 64 + rl) * 128;
    const uint32_t Bbase0 = sb + (uint32_t)(CTA_M + wn * 64 + rl) * 128;

    for (int step = 0; step < NSTEP; ++step) {
        const int buf = step % NSTAGE;
        if (step < NSTEP - 1) {
            asm volatile("cp.async.wait_group 1;" ::: "memory");
        } else {
            asm volatile("cp.async.wait_group 0;" ::: "memory");
        }
        __syncthreads();
        if (step + 2 < NSTEP)
            issue_stage(tid, m0, n0, step + 2, (step + 2) % NSTAGE, sb);

        const uint32_t Ab = Abase0 + buf * STAGE_BYTES;
        const uint32_t Bb = Bbase0 + buf * STAGE_BYTES;

#pragma unroll
        for (int kk = 0; kk < 4; ++kk) {
            const uint32_t co = (uint32_t)(((kk * 2 + cl) ^ sx) << 4);
            uint32_t a[4][4];
#pragma unroll
            for (int mi = 0; mi < 4; ++mi)
                ldsm4(a[mi], Ab + mi * 16 * 128 + co);
            uint32_t b[8][2];
#pragma unroll
            for (int nj = 0; nj < 4; ++nj) {
                uint32_t r[4];
                ldsm4(r, Bb + nj * 16 * 128 + co);
                b[2 * nj][0]     = r[0];
                b[2 * nj + 1][0] = r[1];
                b[2 * nj][1]     = r[2];
                b[2 * nj + 1][1] = r[3];
            }
#pragma unroll
            for (int mi = 0; mi < 4; ++mi)
#pragma unroll
                for (int ni = 0; ni < 8; ++ni)
                    mma16816(acc[mi][ni], a[mi], b[ni]);
        }
    }

    const int rbase = m0 + wm * 64 + (lane >> 2);
    const int cbase = n0 + wn * 64 + (lane & 3) * 2;
#pragma unroll
    for (int mi = 0; mi < 4; ++mi) {
#pragma unroll
        for (int ni = 0; ni < 8; ++ni) {
            float2* p0 = (float2*)&g_z[(size_t)(rbase + mi * 16)     * N_OUT + cbase + ni * 8];
            float2* p1 = (float2*)&g_z[(size_t)(rbase + mi * 16 + 8) * N_OUT + cbase + ni * 8];
            *p0 = make_float2(acc[mi][ni][0], acc[mi][ni][1]);
            *p1 = make_float2(acc[mi][ni][2], acc[mi][ni][3]);
        }
    }
}

// ===========================================================================
// K3: out = fwht(z) * SV.  2 rows per CTA (256 thr).
// ===========================================================================
__global__ __launch_bounds__(256) void epi_kernel(
    const float* __restrict__ SV, float* __restrict__ out)
{
    __shared__ float sm[2 * 4224];
    float* s0 = sm;
    float* s1 = sm + 4224;
    const int t = threadIdx.x;
    const size_t b0 = (size_t)(2 * blockIdx.x)     * N_OUT;
    const size_t b1 = (size_t)(2 * blockIdx.x + 1) * N_OUT;

    float v0[16], v1[16];
    const float4* z0p = (const float4*)(g_z + b0) + 4 * t;
    const float4* z1p = (const float4*)(g_z + b1) + 4 * t;
#pragma unroll
    for (int q = 0; q < 4; ++q) {
        float4 a = z0p[q], c = z1p[q];
        v0[4*q]=a.x; v0[4*q+1]=a.y; v0[4*q+2]=a.z; v0[4*q+3]=a.w;
        v1[4*q]=c.x; v1[4*q+1]=c.y; v1[4*q+2]=c.z; v1[4*q+3]=c.w;
    }

    fwht_local16(v0); fwht_local16(v1);
    fwht_shfl(v0, t); fwht_shfl(v1, t);
    fwht_transpose2(v0, v1, s0, s1, t);
    fwht_local16(v0); fwht_local16(v1);

    const float inv = 0.015625f;
#pragma unroll
    for (int j = 0; j < 16; ++j) {
        const int e = t + 256 * j;
        const float sv = SV[e] * inv;
        out[b0 + e] = v0[j] * sv;
        out[b1 + e] = v1[j] * sv;
    }
}

// ===========================================================================
// launch
// ===========================================================================
extern "C" void kernel_launch(void* const* d_in, const int* in_sizes, int n_args,
                              void* d_out, int out_size) {
    (void)in_sizes; (void)n_args; (void)out_size;
    const float* input   = (const float*)d_in[0];
    const int*   Qidxs   = (const int*)  d_in[1];
    const float* D4_CB   = (const float*)d_in[2];
    const float* SU      = (const float*)d_in[3];
    const float* SV      = (const float*)d_in[4];
    const float* Wscale  = (const float*)d_in[5];
    const float* A       = (const float*)d_in[6];
    const float* B       = (const float*)d_in[7];
    const float* scaleWH = (const float*)d_in[8];
    float* out = (float*)d_out;

    cudaFuncSetAttribute(gemm_kernel,
                         cudaFuncAttributeMaxDynamicSharedMemorySize, SMEM_GEMM);

    prep_kernel<<<PREP_W_BLOCKS + N_ROWS / 2, 256>>>(
        Qidxs, D4_CB, Wscale, A, B, input, SU, scaleWH);
    gemm_kernel<<<dim3(N_OUT / CTA_N, N_ROWS / CTA_M), 256, SMEM_GEMM>>>();
    epi_kernel<<<N_ROWS / 2, 256>>>(SV, out);
}

// round 17
// speedup vs baseline: 1.1982x; 1.0243x over previous
#include <cuda_runtime.h>
#include <cuda_fp16.h>
#include <cstdint>

// ===========================================================================
// QuIP#-style quantized linear, GB300 (base sm_103 target -> mma.sync HMMA).
//   z = fwht( fwht(in/scaleWH*SU) @ (Wscale*W_hat + A@B)^T ) * SV
// K1 prep_w : dequant + fold Wscale + fold A@B -> fp16 W_eff   (own kernel!)
// K2 prep_x : diag scale + reg/shuffle FWHT (2 rows/CTA) -> fp16 x
// K3 gemm   : 128x256 CTA tile, BK=64, 3-stage cp.async, mma.m16n8k16
//             (measured at the mma.sync fp16 hardware floor)
// K4 epi    : reg/shuffle FWHT (2 rows/CTA) + SV -> d_out (fp32)
// R13 lesson: merging prep_w+prep_x into one kernel forced the union
// reg/smem footprint on both paths (occ 36%) — keep them separate.
// ===========================================================================

#define N_ROWS   8192
#define N_IN     4096
#define N_OUT    4096

#define CTA_M 128
#define CTA_N 256
#define BK    64
#define NSTEP (N_IN / BK)                 // 64
#define STAGE_ROWS (CTA_M + CTA_N)        // 384
#define STAGE_BYTES (STAGE_ROWS * 128)    // 49152
#define NSTAGE 3
#define SMEM_GEMM (NSTAGE * STAGE_BYTES)  // 147456

// ---------------- device scratch ----------------
__device__ __half g_x[(size_t)N_ROWS * N_IN];
__device__ __half g_w[(size_t)N_OUT * N_IN];
__device__ float  g_z[(size_t)N_ROWS * N_OUT];

// ---------------- PTX helpers ----------------
__device__ __forceinline__ uint32_t smem_u32(const void* p) {
    uint32_t a;
    asm("{ .reg .u64 t; cvta.to.shared.u64 t, %1; cvt.u32.u64 %0, t; }"
        : "=r"(a) : "l"(p));
    return a;
}
__device__ __forceinline__ void cp_async16(uint32_t saddr, const void* gaddr) {
    asm volatile("cp.async.cg.shared.global [%0], [%1], 16;"
                 :: "r"(saddr), "l"(gaddr) : "memory");
}
__device__ __forceinline__ void ldsm4(uint32_t* r, uint32_t addr) {
    asm volatile("ldmatrix.sync.aligned.m8n8.x4.shared.b16 {%0,%1,%2,%3}, [%4];"
                 : "=r"(r[0]), "=r"(r[1]), "=r"(r[2]), "=r"(r[3]) : "r"(addr));
}
__device__ __forceinline__ void mma16816(float* c, const uint32_t* a, const uint32_t* b) {
    asm volatile(
        "mma.sync.aligned.m16n8k16.row.col.f32.f16.f16.f32 "
        "{%0,%1,%2,%3}, {%4,%5,%6,%7}, {%8,%9}, {%0,%1,%2,%3};"
        : "+f"(c[0]), "+f"(c[1]), "+f"(c[2]), "+f"(c[3])
        : "r"(a[0]), "r"(a[1]), "r"(a[2]), "r"(a[3]), "r"(b[0]), "r"(b[1]));
}

// ---------------- register/shuffle FWHT core (4096 pts, 256 threads) -------
__device__ __forceinline__ void fwht_local16(float* v) {
#pragma unroll
    for (int d = 1; d <= 8; d <<= 1) {
#pragma unroll
        for (int j = 0; j < 16; ++j) {
            if (!(j & d)) {
                float a = v[j], b = v[j | d];
                v[j]     = a + b;
                v[j | d] = a - b;
            }
        }
    }
}
__device__ __forceinline__ void fwht_shfl(float* v, int t) {
#pragma unroll
    for (int m = 1; m <= 8; m <<= 1) {
        const bool hi = (t & m) != 0;
#pragma unroll
        for (int j = 0; j < 16; ++j) {
            float o = __shfl_xor_sync(0xffffffffu, v[j], m);
            v[j] = hi ? (o - v[j]) : (v[j] + o);
        }
    }
}
// Two-row transpose through padded smem (one barrier covers both rows).
__device__ __forceinline__ void fwht_transpose2(float* v0, float* v1,
                                                float* s0, float* s1, int t) {
#pragma unroll
    for (int j = 0; j < 16; ++j) {
        int idx = 16 * t + j;
        s0[idx + (idx >> 5)] = v0[j];
        s1[idx + (idx >> 5)] = v1[j];
    }
    __syncthreads();
#pragma unroll
    for (int j = 0; j < 16; ++j) {
        int idx = t + 256 * j;
        v0[j] = s0[idx + (idx >> 5)];
        v1[j] = s1[idx + (idx >> 5)];
    }
}

// ===========================================================================
// K1: W_eff = Wscale*D4_CB[Qidxs] + A@B  ->  g_w (fp16)
// ===========================================================================
__global__ __launch_bounds__(256) void prep_w_kernel(
    const int*   __restrict__ Qidxs,   // [N_OUT][1024]
    const float* __restrict__ CB,      // [256][4]
    const float* __restrict__ Wsc,     // [1]
    const float* __restrict__ A,       // [N_OUT][64]
    const float* __restrict__ B)       // [64][N_IN]
{
    __shared__ float As[64 * 64];
    __shared__ float Bs[64 * 64];
    __shared__ float CBs[1024];

    const int i0 = blockIdx.x * 64;
    const int o0 = blockIdx.y * 64;
    const int tid = threadIdx.x;

    for (int idx = tid; idx < 64 * 64; idx += 256)
        As[idx] = A[(size_t)(o0 + (idx >> 6)) * 64 + (idx & 63)];
    for (int idx = tid; idx < 64 * 64; idx += 256)
        Bs[idx] = B[(size_t)(idx >> 6) * N_IN + i0 + (idx & 63)];
    for (int idx = tid; idx < 1024; idx += 256)
        CBs[idx] = CB[idx];
    __syncthreads();

    const float ws = Wsc[0];
    const int ob = (tid >> 4) * 4;
    const int ib = (tid & 15) * 4;

    float acc[4][4];
#pragma unroll
    for (int m = 0; m < 4; ++m)
#pragma unroll
        for (int j = 0; j < 4; ++j) acc[m][j] = 0.0f;

#pragma unroll 8
    for (int r = 0; r < 64; ++r) {
        float av[4], bv[4];
#pragma unroll
        for (int m = 0; m < 4; ++m) av[m] = As[(ob + m) * 64 + r];
#pragma unroll
        for (int j = 0; j < 4; ++j) bv[j] = Bs[r * 64 + ib + j];
#pragma unroll
        for (int m = 0; m < 4; ++m)
#pragma unroll
            for (int j = 0; j < 4; ++j) acc[m][j] = fmaf(av[m], bv[j], acc[m][j]);
    }

#pragma unroll
    for (int m = 0; m < 4; ++m) {
        const int o = o0 + ob + m;
        const int q = Qidxs[(size_t)o * (N_IN / 4) + ((i0 + ib) >> 2)];
#pragma unroll
        for (int j = 0; j < 4; ++j) {
            const int i = i0 + ib + j;
            float w = fmaf(ws, CBs[(q << 2) + j], acc[m][j]);
            g_w[(size_t)o * N_IN + i] = __float2half_rn(w);
        }
    }
}

// ===========================================================================
// K2: x = fwht(in*SU/scaleWH) -> g_x (fp16). 2 rows per CTA (256 thr).
// ===========================================================================
__global__ __launch_bounds__(256) void prep_x_kernel(
    const float* __restrict__ in,
    const float* __restrict__ SU,
    const float* __restrict__ scaleWH)
{
    __shared__ float sm[2 * 4224];
    float* s0 = sm;
    float* s1 = sm + 4224;
    const int t = threadIdx.x;
    const size_t b0 = (size_t)(2 * blockIdx.x)     * N_IN;
    const size_t b1 = (size_t)(2 * blockIdx.x + 1) * N_IN;

    float v0[16], v1[16];
    const float4* sp  = (const float4*)SU + 4 * t;
    const float4* wp  = (const float4*)scaleWH + 4 * t;
    const float4* i0p = (const float4*)(in + b0) + 4 * t;
    const float4* i1p = (const float4*)(in + b1) + 4 * t;
#pragma unroll
    for (int q = 0; q < 4; ++q) {
        float4 a = i0p[q], c = i1p[q], su = sp[q], sw = wp[q];
        float f0 = su.x / sw.x, f1 = su.y / sw.y;
        float f2 = su.z / sw.z, f3 = su.w / sw.w;
        v0[4*q]   = a.x * f0;  v0[4*q+1] = a.y * f1;
        v0[4*q+2] = a.z * f2;  v0[4*q+3] = a.w * f3;
        v1[4*q]   = c.x * f0;  v1[4*q+1] = c.y * f1;
        v1[4*q+2] = c.z * f2;  v1[4*q+3] = c.w * f3;
    }

    fwht_local16(v0); fwht_local16(v1);
    fwht_shfl(v0, t); fwht_shfl(v1, t);
    fwht_transpose2(v0, v1, s0, s1, t);
    fwht_local16(v0); fwht_local16(v1);

    const float inv = 0.015625f;  // 1/sqrt(4096)
#pragma unroll
    for (int j = 0; j < 16; ++j) {
        g_x[b0 + t + 256 * j] = __float2half_rn(v0[j] * inv);
        g_x[b1 + t + 256 * j] = __float2half_rn(v1[j] * inv);
    }
}

// ===========================================================================
// K3: GEMM  g_z = g_x (8192x4096) * g_w^T (4096x4096), fp16 in / fp32 acc.
// ===========================================================================
__device__ __forceinline__ void issue_stage(int tid, int m0, int n0,
                                            int step, int buf, uint32_t sb) {
    const int kb = step * BK;
    const uint32_t base = sb + buf * STAGE_BYTES;
#pragma unroll
    for (int i = 0; i < (STAGE_ROWS * 8) / 256; ++i) {   // 12
        const int idx = tid + i * 256;
        const int row = idx >> 3;
        const int ch  = idx & 7;
        const uint32_t saddr = base + row * 128 + ((ch ^ (row & 7)) << 4);
        const __half* g = (row < CTA_M)
            ? g_x + (size_t)(m0 + row) * N_IN + kb + ch * 8
            : g_w + (size_t)(n0 + row - CTA_M) * N_IN + kb + ch * 8;
        cp_async16(saddr, g);
    }
    asm volatile("cp.async.commit_group;" ::: "memory");
}

__global__ __launch_bounds__(256) void gemm_kernel() {
    extern __shared__ char smem[];
    const uint32_t sb = smem_u32(smem);
    const int tid  = threadIdx.x;
    const int lane = tid & 31;
    const int wid  = tid >> 5;
    const int wm   = wid >> 2;
    const int wn   = wid & 3;
    const int m0   = blockIdx.y * CTA_M;
    const int n0   = blockIdx.x * CTA_N;

    const int rl = lane & 15;
    const int cl = lane >> 4;
    const int sx = rl & 7;

    float acc[4][8][4];
#pragma unroll
    for (int mi = 0; mi < 4; ++mi)
#pragma unroll
        for (int ni = 0; ni < 8; ++ni)
#pragma unroll
            for (int q = 0; q < 4; ++q) acc[mi][ni][q] = 0.0f;

    issue_stage(tid, m0, n0, 0, 0, sb);
    issue_stage(tid, m0, n0, 1, 1, sb);

    const uint32_t Abase0 = sb + (uint32_t)(wm * 64 + rl) * 128;
    const uint32_t Bbase0 = sb + (uint32_t)(CTA_M + wn * 64 + rl) * 128;

    for (int step = 0; step < NSTEP; ++step) {
        const int buf = step % NSTAGE;
        if (step < NSTEP - 1) {
            asm volatile("cp.async.wait_group 1;" ::: "memory");
        } else {
            asm volatile("cp.async.wait_group 0;" ::: "memory");
        }
        __syncthreads();
        if (step + 2 < NSTEP)
            issue_stage(tid, m0, n0, step + 2, (step + 2) % NSTAGE, sb);

        const uint32_t Ab = Abase0 + buf * STAGE_BYTES;
        const uint32_t Bb = Bbase0 + buf * STAGE_BYTES;

#pragma unroll
        for (int kk = 0; kk < 4; ++kk) {
            const uint32_t co = (uint32_t)(((kk * 2 + cl) ^ sx) << 4);
            uint32_t a[4][4];
#pragma unroll
            for (int mi = 0; mi < 4; ++mi)
                ldsm4(a[mi], Ab + mi * 16 * 128 + co);
            uint32_t b[8][2];
#pragma unroll
            for (int nj = 0; nj < 4; ++nj) {
                uint32_t r[4];
                ldsm4(r, Bb + nj * 16 * 128 + co);
                b[2 * nj][0]     = r[0];
                b[2 * nj + 1][0] = r[1];
                b[2 * nj][1]     = r[2];
                b[2 * nj + 1][1] = r[3];
            }
#pragma unroll
            for (int mi = 0; mi < 4; ++mi)
#pragma unroll
                for (int ni = 0; ni < 8; ++ni)
                    mma16816(acc[mi][ni], a[mi], b[ni]);
        }
    }

    const int rbase = m0 + wm * 64 + (lane >> 2);
    const int cbase = n0 + wn * 64 + (lane & 3) * 2;
#pragma unroll
    for (int mi = 0; mi < 4; ++mi) {
#pragma unroll
        for (int ni = 0; ni < 8; ++ni) {
            float2* p0 = (float2*)&g_z[(size_t)(rbase + mi * 16)     * N_OUT + cbase + ni * 8];
            float2* p1 = (float2*)&g_z[(size_t)(rbase + mi * 16 + 8) * N_OUT + cbase + ni * 8];
            *p0 = make_float2(acc[mi][ni][0], acc[mi][ni][1]);
            *p1 = make_float2(acc[mi][ni][2], acc[mi][ni][3]);
        }
    }
}

// ===========================================================================
// K4: out = fwht(z) * SV.  2 rows per CTA (256 thr).
// ===========================================================================
__global__ __launch_bounds__(256) void epi_kernel(
    const float* __restrict__ SV, float* __restrict__ out)
{
    __shared__ float sm[2 * 4224];
    float* s0 = sm;
    float* s1 = sm + 4224;
    const int t = threadIdx.x;
    const size_t b0 = (size_t)(2 * blockIdx.x)     * N_OUT;
    const size_t b1 = (size_t)(2 * blockIdx.x + 1) * N_OUT;

    float v0[16], v1[16];
    const float4* z0p = (const float4*)(g_z + b0) + 4 * t;
    const float4* z1p = (const float4*)(g_z + b1) + 4 * t;
#pragma unroll
    for (int q = 0; q < 4; ++q) {
        float4 a = z0p[q], c = z1p[q];
        v0[4*q]=a.x; v0[4*q+1]=a.y; v0[4*q+2]=a.z; v0[4*q+3]=a.w;
        v1[4*q]=c.x; v1[4*q+1]=c.y; v1[4*q+2]=c.z; v1[4*q+3]=c.w;
    }

    fwht_local16(v0); fwht_local16(v1);
    fwht_shfl(v0, t); fwht_shfl(v1, t);
    fwht_transpose2(v0, v1, s0, s1, t);
    fwht_local16(v0); fwht_local16(v1);

    const float inv = 0.015625f;
#pragma unroll
    for (int j = 0; j < 16; ++j) {
        const int e = t + 256 * j;
        const float sv = SV[e] * inv;
        out[b0 + e] = v0[j] * sv;
        out[b1 + e] = v1[j] * sv;
    }
}

// ===========================================================================
// launch
// ===========================================================================
extern "C" void kernel_launch(void* const* d_in, const int* in_sizes, int n_args,
                              void* d_out, int out_size) {
    (void)in_sizes; (void)n_args; (void)out_size;
    const float* input   = (const float*)d_in[0];
    const int*   Qidxs   = (const int*)  d_in[1];
    const float* D4_CB   = (const float*)d_in[2];
    const float* SU      = (const float*)d_in[3];
    const float* SV      = (const float*)d_in[4];
    const float* Wscale  = (const float*)d_in[5];
    const float* A       = (const float*)d_in[6];
    const float* B       = (const float*)d_in[7];
    const float* scaleWH = (const float*)d_in[8];
    float* out = (float*)d_out;

    cudaFuncSetAttribute(gemm_kernel,
                         cudaFuncAttributeMaxDynamicSharedMemorySize, SMEM_GEMM);

    prep_w_kernel<<<dim3(N_IN / 64, N_OUT / 64), 256>>>(Qidxs, D4_CB, Wscale, A, B);
    prep_x_kernel<<<N_ROWS / 2, 256>>>(input, SU, scaleWH);
    gemm_kernel<<<dim3(N_OUT / CTA_N, N_ROWS / CTA_M), 256, SMEM_GEMM>>>();
    epi_kernel<<<N_ROWS / 2, 256>>>(SV, out);
}